// round 15
// baseline (speedup 1.0000x reference)
#include <cuda_runtime.h>
#include <math.h>
#include <stdint.h>

// Problem constants (fixed by the reference)
#define BB      32
#define SS      4096
#define HQN     32
#define HKVN    8
#define GG      4          // HQN / HKVN
#define DD      128
#define NSPLIT  32
#define CHUNK   (SS / NSPLIT)   // 128
#define KVROW   (HKVN * DD)     // 1024 floats between consecutive s rows
#define SCALE_F 0.088388347648318447f   // 1/sqrt(128)
// p = exp(sc - 30), sc = 30*tanh(dot*SCALE/30)  =>  p = exp(-60/(exp(dot*SCALE/15)+1))
#define C2_F    (SCALE_F / 15.0f)
#define NSTAGE  4          // cp.async pipeline depth (8 KB per stage)

// Dense accumulators (fixed softmax shift m=30 -> combination is LINEAR).
// Zero-initialized at module load; the last CTA per (b,h) resets them after
// reading, so every graph replay sees zeros. No allocations -> __device__.
__device__ float g_oacc[(size_t)BB * HKVN * GG * DD];   // 512 KB
__device__ float g_lacc[(size_t)BB * HKVN * GG];
__device__ unsigned int g_cnt[BB * HKVN];               // last-CTA counters

typedef unsigned long long u64;

__device__ __forceinline__ void fma2(u64 &d, u64 a, u64 b) {
    asm("fma.rn.f32x2 %0, %1, %2, %0;" : "+l"(d) : "l"(a), "l"(b));
}
__device__ __forceinline__ u64 pk(float x, float y) {
    u64 r; asm("mov.b64 %0, {%1, %2};" : "=l"(r) : "f"(x), "f"(y)); return r;
}
__device__ __forceinline__ float usum(u64 v) {
    float lo, hi; asm("mov.b64 {%0, %1}, %2;" : "=f"(lo), "=f"(hi) : "l"(v));
    return lo + hi;
}
// plain cp.async (the L2::cache_hint form traps on sm_103a - R11 post-mortem)
__device__ __forceinline__ void cp16(uint32_t dst, const void* src) {
    asm volatile("cp.async.cg.shared.global [%0], [%1], 16;" :: "r"(dst), "l"(src));
}
#define CP_COMMIT()  asm volatile("cp.async.commit_group;" ::: "memory")
#define CP_WAIT(N)   asm volatile("cp.async.wait_group %0;" :: "n"(N) : "memory")

struct Buf {
    u64 k[4];
    u64 v[4];
    bool ok;
};

struct WState {
    u64 q2[GG][4];
    u64 acc[GG][4];
    float l[GG];
};

// kv stage buffer and post-loop reduction scratch are temporally disjoint -> union
union SmemU {
    float4 kv[NSTAGE * 8 * 64];            // 32 KB
    struct {
        float acc[4][GG][DD];              // 8 KB
        float l[4][GG];
    } red;
};

// Process one s position per half-warp (2 s per warp per call).
__device__ __forceinline__ void body(WState &st, const Buf &bf)
{
    float d[GG];
#pragma unroll
    for (int g = 0; g < GG; g++) {
        u64 t = pk(0.f, 0.f);
        fma2(t, st.q2[g][0], bf.k[0]);
        fma2(t, st.q2[g][1], bf.k[1]);
        fma2(t, st.q2[g][2], bf.k[2]);
        fma2(t, st.q2[g][3], bf.k[3]);
        d[g] = usum(t);
    }
#pragma unroll
    for (int off = 8; off > 0; off >>= 1) {
#pragma unroll
        for (int g = 0; g < GG; g++)
            d[g] += __shfl_xor_sync(0xffffffffu, d[g], off);
    }
#pragma unroll
    for (int g = 0; g < GG; g++) {
        float t = __expf(d[g] * C2_F);
        float p = __expf(__fdividef(-60.0f, t + 1.0f));
        p = bf.ok ? p : 0.0f;
        st.l[g] += p;
        u64 pp = pk(p, p);
        fma2(st.acc[g][0], pp, bf.v[0]);
        fma2(st.acc[g][1], pp, bf.v[1]);
        fma2(st.acc[g][2], pp, bf.v[2]);
        fma2(st.acc[g][3], pp, bf.v[3]);
    }
}

__global__ void __launch_bounds__(128, 5)
attn_fused_kernel(const float* __restrict__ q,
                  const float* __restrict__ knew,
                  const float* __restrict__ vnew,
                  const float* __restrict__ kc,
                  const float* __restrict__ vc,
                  const int*   __restrict__ seq_lens,
                  float*       __restrict__ out)
{
    const int h     = blockIdx.x;
    const int split = blockIdx.y;
    const int b     = blockIdx.z;
    const int tid   = threadIdx.x;
    const int w     = tid >> 5;          // 4 warps
    const int lane  = tid & 31;
    const int half  = lane >> 4;
    const int lh    = lane & 15;
    // conflict-free lane ownership: float4 idx lh and 16+lh
    const int dcolA = lh * 4;            // d columns [dcolA, dcolA+4)
    const int dcolB = 64 + lh * 4;       // d columns [dcolB, dcolB+4)

    const int seq_len = seq_lens[b];
    const int start   = split * CHUNK;

    if (start >= seq_len) return;        // contributes nothing

    __shared__ SmemU su;
    __shared__ unsigned int s_islast;

    const int n_valid = min(NSPLIT, (seq_len + CHUNK - 1) / CHUNK);

    WState st;
    {
        const float* qb = q + (size_t)b * HQN * DD + (size_t)h * GG * DD;
#pragma unroll
        for (int g = 0; g < GG; g++) {
            float4 qa = *(const float4*)(qb + (size_t)g * DD + dcolA);
            float4 qc = *(const float4*)(qb + (size_t)g * DD + dcolB);
            st.q2[g][0] = pk(qa.x, qa.y);
            st.q2[g][1] = pk(qa.z, qa.w);
            st.q2[g][2] = pk(qc.x, qc.y);
            st.q2[g][3] = pk(qc.z, qc.w);
            st.acc[g][0] = st.acc[g][1] = st.acc[g][2] = st.acc[g][3] = pk(0.f, 0.f);
            st.l[g] = 0.f;
        }
    }

    const int end_c = min(start + CHUNK, seq_len - 1);   // cache rows only
    const float* kbase = kc + ((size_t)b * SS) * KVROW + (size_t)h * DD;
    const float* vbase = vc + ((size_t)b * SS) * KVROW + (size_t)h * DD;

    const int span = end_c - start;
    const int n_it = (span > 0) ? ((span + 7) >> 3) : 0;

    const uint32_t smem_kv = (uint32_t)__cvta_generic_to_shared(su.kv);

    // cooperative fetch of one stage (8 s rows of K and V, 8 KB), 4 x 16B per thread
#define ISSUE_STAGE(STG, SBASE)                                            \
    do {                                                                   \
        _Pragma("unroll")                                                  \
        for (int j = 0; j < 4; j++) {                                      \
            int ci  = tid + j * 128;        /* 0..511 */                   \
            int row = ci >> 6;                                             \
            int sub = ci & 63;                                             \
            int isv = sub >> 5;                                            \
            int col = sub & 31;                                            \
            int s   = (SBASE) + row;                                       \
            s = (s < end_c) ? s : (end_c - 1);                             \
            const float* srcp = (isv ? vbase : kbase) + (size_t)s * KVROW + col * 4; \
            uint32_t dst = smem_kv + (uint32_t)((((STG) * 8 + row) * 64 + isv * 32 + col) * 16); \
            cp16(dst, srcp);                                               \
        }                                                                  \
    } while (0)

    if (n_it > 0) {
        // prologue: fill NSTAGE-1 stages
#pragma unroll
        for (int p = 0; p < NSTAGE - 1; p++) {
            if (p < n_it) ISSUE_STAGE(p, start + p * 8);
            CP_COMMIT();
        }

        const int row = w * 2 + half;     // this half-warp's row within a stage
        for (int it = 0; it < n_it; it++) {
            CP_WAIT(NSTAGE - 2);
            __syncthreads();

            const int stg = it & (NSTAGE - 1);
            const float4* b4 = su.kv + (stg * 8 + row) * 64;
            // conflict-free: 8 consecutive lanes read 128 contiguous bytes
            float4 k0 = b4[lh],      k1 = b4[16 + lh];
            float4 v0 = b4[32 + lh], v1 = b4[48 + lh];
            Buf bf;
            bf.ok = (start + it * 8 + row) < end_c;
            bf.k[0] = pk(k0.x, k0.y); bf.k[1] = pk(k0.z, k0.w);
            bf.k[2] = pk(k1.x, k1.y); bf.k[3] = pk(k1.z, k1.w);
            bf.v[0] = pk(v0.x, v0.y); bf.v[1] = pk(v0.z, v0.w);
            bf.v[2] = pk(v1.x, v1.y); bf.v[3] = pk(v1.z, v1.w);
            body(st, bf);

            const int pf = it + NSTAGE - 1;
            if (pf < n_it) ISSUE_STAGE(pf & (NSTAGE - 1), start + pf * 8);
            CP_COMMIT();
        }
    }

    // new token (s = seq_len-1), handled once by warp 0 / half 0
    const int last = seq_len - 1;
    if (w == 0 && last >= start && last < start + CHUNK) {
        const float* kp = knew + ((size_t)b * HKVN + h) * DD;
        const float* vp = vnew + ((size_t)b * HKVN + h) * DD;
        Buf nb;
        nb.ok = (half == 0);
        float4 ka  = *(const float4*)(kp + dcolA);
        float4 kc4 = *(const float4*)(kp + dcolB);
        float4 va  = *(const float4*)(vp + dcolA);
        float4 vc4 = *(const float4*)(vp + dcolB);
        nb.k[0] = pk(ka.x, ka.y);   nb.k[1] = pk(ka.z, ka.w);
        nb.k[2] = pk(kc4.x, kc4.y); nb.k[3] = pk(kc4.z, kc4.w);
        nb.v[0] = pk(va.x, va.y);   nb.v[1] = pk(va.z, va.w);
        nb.v[2] = pk(vc4.x, vc4.y); nb.v[3] = pk(vc4.z, vc4.w);
        body(st, nb);
    }

    // fold halves (registers only)
#pragma unroll
    for (int g = 0; g < GG; g++) {
#pragma unroll
        for (int j = 0; j < 4; j++) {
            u64 o = __shfl_xor_sync(0xffffffffu, st.acc[g][j], 16);
            float2 a = *(float2*)&st.acc[g][j];
            float2 ob = *(float2*)&o;
            a.x += ob.x; a.y += ob.y;
            st.acc[g][j] = pk(a.x, a.y);
        }
        st.l[g] += __shfl_xor_sync(0xffffffffu, st.l[g], 16);
    }

    // union switchover: all cp.async drained, all warps past their kv reads
    CP_WAIT(0);
    __syncthreads();

    if (half == 0) {
#pragma unroll
        for (int g = 0; g < GG; g++) {
            u64* dstA = (u64*)&su.red.acc[w][g][dcolA];
            u64* dstB = (u64*)&su.red.acc[w][g][dcolB];
            dstA[0] = st.acc[g][0]; dstA[1] = st.acc[g][1];
            dstB[0] = st.acc[g][2]; dstB[1] = st.acc[g][3];
            if (lh == 0) su.red.l[w][g] = st.l[g];
        }
    }
    __syncthreads();

    // combine 4 warps, then LINEAR atomic accumulation into the dense output
    // accumulator (fixed softmax shift m=30 makes split combination a plain sum)
    const size_t obase = ((size_t)(b * HKVN + h)) * GG;
    for (int i = tid; i < GG * DD; i += 128) {
        int g = i >> 7, d = i & 127;
        float a = su.red.acc[0][g][d] + su.red.acc[1][g][d]
                + su.red.acc[2][g][d] + su.red.acc[3][g][d];
        atomicAdd(&g_oacc[(obase + g) * DD + d], a);
    }
    if (tid < GG) {
        float L = su.red.l[0][tid] + su.red.l[1][tid]
                + su.red.l[2][tid] + su.red.l[3][tid];
        atomicAdd(&g_lacc[obase + tid], L);
    }

    // ---- last-CTA-per-(b,h) divide (accumulators are L2-hot) ----
    __threadfence();                     // order our REDs before the signal
    __syncthreads();
    if (tid == 0) {
        unsigned int old = atomicAdd(&g_cnt[b * HKVN + h], 1u);
        s_islast = (old == (unsigned int)(n_valid - 1)) ? 1u : 0u;
    }
    __syncthreads();
    if (!s_islast) return;
    __threadfence();                     // acquire: peer REDs visible

    {
        const int g  = tid >> 5;
        const int d4 = (tid & 31) * 4;
        const size_t base = obase + g;

        float l = g_lacc[base];
        float4 a = *(const float4*)&g_oacc[base * DD + d4];
        float inv = 1.0f / l;
        float4 o = make_float4(a.x * inv, a.y * inv, a.z * inv, a.w * inv);
        *(float4*)&out[(size_t)b * HQN * DD + (size_t)(h * GG + g) * DD + d4] = o;

        // reset for the next graph replay (only we can touch these now)
        *(float4*)&g_oacc[base * DD + d4] = make_float4(0.f, 0.f, 0.f, 0.f);
        if ((tid & 31) == 0) g_lacc[base] = 0.f;
        if (tid == 0) g_cnt[b * HKVN + h] = 0u;
    }
#undef ISSUE_STAGE
}

extern "C" void kernel_launch(void* const* d_in, const int* in_sizes, int n_in,
                              void* d_out, int out_size)
{
    const float* q    = (const float*)d_in[0];
    const float* knew = (const float*)d_in[1];
    const float* vnew = (const float*)d_in[2];
    const float* kc   = (const float*)d_in[3];
    const float* vc   = (const float*)d_in[4];
    const int*   sl   = (const int*)  d_in[5];
    float* out = (float*)d_out;

    dim3 grid(HKVN, NSPLIT, BB);
    attn_fused_kernel<<<grid, 128>>>(q, knew, vnew, kc, vc, sl, out);
}

// round 16
// speedup vs baseline: 1.1920x; 1.1920x over previous
#include <cuda_runtime.h>
#include <math.h>
#include <stdint.h>

// Problem constants (fixed by the reference)
#define BB      32
#define SS      4096
#define HQN     32
#define HKVN    8
#define GG      4          // HQN / HKVN
#define DD      128
#define NSPLIT  32
#define CHUNK   (SS / NSPLIT)   // 128
#define KVROW   (HKVN * DD)     // 1024 floats between consecutive s rows
#define SCALE_F 0.088388347648318447f   // 1/sqrt(128)
// p = exp(sc - 30), sc = 30*tanh(dot*SCALE/30)  =>  p = exp(-60/(exp(dot*SCALE/15)+1))
#define C2_F    (SCALE_F / 15.0f)
#define NSTAGE  4          // cp.async pipeline depth (8 KB per stage)

// Dense accumulators (fixed softmax shift m=30 -> combination is LINEAR).
// Zero-initialized at module load; the divide kernel resets them to zero after
// each use, so every graph replay sees zeros. No allocations -> __device__.
__device__ float g_oacc[(size_t)BB * HKVN * GG * DD];   // 512 KB
__device__ float g_lacc[(size_t)BB * HKVN * GG];

typedef unsigned long long u64;

__device__ __forceinline__ void fma2(u64 &d, u64 a, u64 b) {
    asm("fma.rn.f32x2 %0, %1, %2, %0;" : "+l"(d) : "l"(a), "l"(b));
}
__device__ __forceinline__ u64 pk(float x, float y) {
    u64 r; asm("mov.b64 %0, {%1, %2};" : "=l"(r) : "f"(x), "f"(y)); return r;
}
__device__ __forceinline__ float usum(u64 v) {
    float lo, hi; asm("mov.b64 {%0, %1}, %2;" : "=f"(lo), "=f"(hi) : "l"(v));
    return lo + hi;
}
// plain cp.async (the L2::cache_hint form traps on sm_103a - R11 post-mortem)
__device__ __forceinline__ void cp16(uint32_t dst, const void* src) {
    asm volatile("cp.async.cg.shared.global [%0], [%1], 16;" :: "r"(dst), "l"(src));
}
#define CP_COMMIT()  asm volatile("cp.async.commit_group;" ::: "memory")
#define CP_WAIT(N)   asm volatile("cp.async.wait_group %0;" :: "n"(N) : "memory")

struct Buf {
    u64 k[4];
    u64 v[4];
    bool ok;
};

struct WState {
    u64 q2[GG][4];
    u64 acc[GG][4];
    float l[GG];
};

// kv stage buffer and post-loop reduction scratch are temporally disjoint -> union
union SmemU {
    float4 kv[NSTAGE * 8 * 64];            // 32 KB
    struct {
        float acc[4][GG][DD];              // 8 KB
        float l[4][GG];
    } red;
};

// Process one s position per half-warp (2 s per warp per call).
__device__ __forceinline__ void body(WState &st, const Buf &bf)
{
    float d[GG];
#pragma unroll
    for (int g = 0; g < GG; g++) {
        u64 t = pk(0.f, 0.f);
        fma2(t, st.q2[g][0], bf.k[0]);
        fma2(t, st.q2[g][1], bf.k[1]);
        fma2(t, st.q2[g][2], bf.k[2]);
        fma2(t, st.q2[g][3], bf.k[3]);
        d[g] = usum(t);
    }
#pragma unroll
    for (int off = 8; off > 0; off >>= 1) {
#pragma unroll
        for (int g = 0; g < GG; g++)
            d[g] += __shfl_xor_sync(0xffffffffu, d[g], off);
    }
#pragma unroll
    for (int g = 0; g < GG; g++) {
        float t = __expf(d[g] * C2_F);
        float p = __expf(__fdividef(-60.0f, t + 1.0f));
        p = bf.ok ? p : 0.0f;
        st.l[g] += p;
        u64 pp = pk(p, p);
        fma2(st.acc[g][0], pp, bf.v[0]);
        fma2(st.acc[g][1], pp, bf.v[1]);
        fma2(st.acc[g][2], pp, bf.v[2]);
        fma2(st.acc[g][3], pp, bf.v[3]);
    }
}

__global__ void __launch_bounds__(128, 5)
attn_partial_kernel(const float* __restrict__ q,
                    const float* __restrict__ knew,
                    const float* __restrict__ vnew,
                    const float* __restrict__ kc,
                    const float* __restrict__ vc,
                    const int*   __restrict__ seq_lens)
{
    const int h     = blockIdx.x;
    const int split = blockIdx.y;
    const int b     = blockIdx.z;
    const int tid   = threadIdx.x;
    const int w     = tid >> 5;          // 4 warps
    const int lane  = tid & 31;
    const int half  = lane >> 4;
    const int lh    = lane & 15;
    // conflict-free lane ownership: float4 idx lh and 16+lh
    const int dcolA = lh * 4;            // d columns [dcolA, dcolA+4)
    const int dcolB = 64 + lh * 4;       // d columns [dcolB, dcolB+4)

    const int seq_len = seq_lens[b];
    const int start   = split * CHUNK;

    if (start >= seq_len) return;        // contributes nothing

    __shared__ SmemU su;

    WState st;
    {
        const float* qb = q + (size_t)b * HQN * DD + (size_t)h * GG * DD;
#pragma unroll
        for (int g = 0; g < GG; g++) {
            float4 qa = *(const float4*)(qb + (size_t)g * DD + dcolA);
            float4 qc = *(const float4*)(qb + (size_t)g * DD + dcolB);
            st.q2[g][0] = pk(qa.x, qa.y);
            st.q2[g][1] = pk(qa.z, qa.w);
            st.q2[g][2] = pk(qc.x, qc.y);
            st.q2[g][3] = pk(qc.z, qc.w);
            st.acc[g][0] = st.acc[g][1] = st.acc[g][2] = st.acc[g][3] = pk(0.f, 0.f);
            st.l[g] = 0.f;
        }
    }

    const int end_c = min(start + CHUNK, seq_len - 1);   // cache rows only
    const float* kbase = kc + ((size_t)b * SS) * KVROW + (size_t)h * DD;
    const float* vbase = vc + ((size_t)b * SS) * KVROW + (size_t)h * DD;

    const int span = end_c - start;
    const int n_it = (span > 0) ? ((span + 7) >> 3) : 0;

    const uint32_t smem_kv = (uint32_t)__cvta_generic_to_shared(su.kv);

    // cooperative fetch of one stage (8 s rows of K and V, 8 KB), 4 x 16B per thread
#define ISSUE_STAGE(STG, SBASE)                                            \
    do {                                                                   \
        _Pragma("unroll")                                                  \
        for (int j = 0; j < 4; j++) {                                      \
            int ci  = tid + j * 128;        /* 0..511 */                   \
            int row = ci >> 6;                                             \
            int sub = ci & 63;                                             \
            int isv = sub >> 5;                                            \
            int col = sub & 31;                                            \
            int s   = (SBASE) + row;                                       \
            s = (s < end_c) ? s : (end_c - 1);                             \
            const float* srcp = (isv ? vbase : kbase) + (size_t)s * KVROW + col * 4; \
            uint32_t dst = smem_kv + (uint32_t)((((STG) * 8 + row) * 64 + isv * 32 + col) * 16); \
            cp16(dst, srcp);                                               \
        }                                                                  \
    } while (0)

    if (n_it > 0) {
        // prologue: fill NSTAGE-1 stages
#pragma unroll
        for (int p = 0; p < NSTAGE - 1; p++) {
            if (p < n_it) ISSUE_STAGE(p, start + p * 8);
            CP_COMMIT();
        }

        const int row = w * 2 + half;     // this half-warp's row within a stage
        for (int it = 0; it < n_it; it++) {
            CP_WAIT(NSTAGE - 2);
            __syncthreads();

            const int stg = it & (NSTAGE - 1);
            const float4* b4 = su.kv + (stg * 8 + row) * 64;
            // conflict-free: 8 consecutive lanes read 128 contiguous bytes
            float4 k0 = b4[lh],      k1 = b4[16 + lh];
            float4 v0 = b4[32 + lh], v1 = b4[48 + lh];
            Buf bf;
            bf.ok = (start + it * 8 + row) < end_c;
            bf.k[0] = pk(k0.x, k0.y); bf.k[1] = pk(k0.z, k0.w);
            bf.k[2] = pk(k1.x, k1.y); bf.k[3] = pk(k1.z, k1.w);
            bf.v[0] = pk(v0.x, v0.y); bf.v[1] = pk(v0.z, v0.w);
            bf.v[2] = pk(v1.x, v1.y); bf.v[3] = pk(v1.z, v1.w);
            body(st, bf);

            const int pf = it + NSTAGE - 1;
            if (pf < n_it) ISSUE_STAGE(pf & (NSTAGE - 1), start + pf * 8);
            CP_COMMIT();
        }
    }

    // new token (s = seq_len-1), handled once by warp 0 / half 0
    const int last = seq_len - 1;
    if (w == 0 && last >= start && last < start + CHUNK) {
        const float* kp = knew + ((size_t)b * HKVN + h) * DD;
        const float* vp = vnew + ((size_t)b * HKVN + h) * DD;
        Buf nb;
        nb.ok = (half == 0);
        float4 ka  = *(const float4*)(kp + dcolA);
        float4 kc4 = *(const float4*)(kp + dcolB);
        float4 va  = *(const float4*)(vp + dcolA);
        float4 vc4 = *(const float4*)(vp + dcolB);
        nb.k[0] = pk(ka.x, ka.y);   nb.k[1] = pk(ka.z, ka.w);
        nb.k[2] = pk(kc4.x, kc4.y); nb.k[3] = pk(kc4.z, kc4.w);
        nb.v[0] = pk(va.x, va.y);   nb.v[1] = pk(va.z, va.w);
        nb.v[2] = pk(vc4.x, vc4.y); nb.v[3] = pk(vc4.z, vc4.w);
        body(st, nb);
    }

    // fold halves (registers only)
#pragma unroll
    for (int g = 0; g < GG; g++) {
#pragma unroll
        for (int j = 0; j < 4; j++) {
            u64 o = __shfl_xor_sync(0xffffffffu, st.acc[g][j], 16);
            float2 a = *(float2*)&st.acc[g][j];
            float2 ob = *(float2*)&o;
            a.x += ob.x; a.y += ob.y;
            st.acc[g][j] = pk(a.x, a.y);
        }
        st.l[g] += __shfl_xor_sync(0xffffffffu, st.l[g], 16);
    }

    // union switchover: all cp.async drained, all warps past their kv reads
    CP_WAIT(0);
    __syncthreads();

    if (half == 0) {
#pragma unroll
        for (int g = 0; g < GG; g++) {
            u64* dstA = (u64*)&su.red.acc[w][g][dcolA];
            u64* dstB = (u64*)&su.red.acc[w][g][dcolB];
            dstA[0] = st.acc[g][0]; dstA[1] = st.acc[g][1];
            dstB[0] = st.acc[g][2]; dstB[1] = st.acc[g][3];
            if (lh == 0) su.red.l[w][g] = st.l[g];
        }
    }
    __syncthreads();

    // combine 4 warps, then LINEAR atomic accumulation into the dense output
    // accumulator (fixed softmax shift m=30 makes split combination a plain sum).
    // NO per-CTA fence here (R8/R15 lesson): PDL's grid-completion flush
    // provides the ordering for the divide kernel.
    const size_t obase = ((size_t)(b * HKVN + h)) * GG;
    for (int i = tid; i < GG * DD; i += 128) {
        int g = i >> 7, d = i & 127;
        float a = su.red.acc[0][g][d] + su.red.acc[1][g][d]
                + su.red.acc[2][g][d] + su.red.acc[3][g][d];
        atomicAdd(&g_oacc[(obase + g) * DD + d], a);
    }
    if (tid < GG) {
        float L = su.red.l[0][tid] + su.red.l[1][tid]
                + su.red.l[2][tid] + su.red.l[3][tid];
        atomicAdd(&g_lacc[obase + tid], L);
    }
#undef ISSUE_STAGE
}

// Final divide + accumulator reset. Launched with programmatic dependent
// launch: CTAs come up resident while the partial is still streaming, then
// griddepcontrol.wait blocks until the partial grid completes WITH its
// memory flushed. One CTA per (b,h).
__global__ void __launch_bounds__(128)
attn_divide_kernel(float* __restrict__ out)
{
    // wait for the primary grid (partial) to complete + flush
    asm volatile("griddepcontrol.wait;" ::: "memory");

    const int bh = blockIdx.x;           // [0, BB*HKVN)
    const int h  = bh % HKVN;
    const int b  = bh / HKVN;
    const int tid  = threadIdx.x;
    const int g    = tid >> 5;
    const int lane = tid & 31;
    const int d4   = lane * 4;

    const size_t base = ((size_t)(b * HKVN + h)) * GG + g;

    float l = g_lacc[base];
    float4 a = *(const float4*)&g_oacc[base * DD + d4];
    float inv = 1.0f / l;
    float4 o = make_float4(a.x * inv, a.y * inv, a.z * inv, a.w * inv);
    *(float4*)&out[(size_t)b * HQN * DD + (size_t)(h * GG + g) * DD + d4] = o;

    // reset for the next graph replay (ordered after our reads; every slot
    // is covered exactly once across the grid)
    *(float4*)&g_oacc[base * DD + d4] = make_float4(0.f, 0.f, 0.f, 0.f);
    if (lane == 0) g_lacc[base] = 0.f;
}

extern "C" void kernel_launch(void* const* d_in, const int* in_sizes, int n_in,
                              void* d_out, int out_size)
{
    const float* q    = (const float*)d_in[0];
    const float* knew = (const float*)d_in[1];
    const float* vnew = (const float*)d_in[2];
    const float* kc   = (const float*)d_in[3];
    const float* vc   = (const float*)d_in[4];
    const int*   sl   = (const int*)  d_in[5];
    float* out = (float*)d_out;

    dim3 grid(HKVN, NSPLIT, BB);
    attn_partial_kernel<<<grid, 128>>>(q, knew, vnew, kc, vc, sl);

    // divide kernel with programmatic dependent launch (overlaps its launch
    // latency with the partial's tail; griddepcontrol.wait provides ordering)
    cudaLaunchConfig_t cfg = {};
    cfg.gridDim  = dim3(BB * HKVN);
    cfg.blockDim = dim3(128);
    cfg.dynamicSmemBytes = 0;
    cfg.stream = 0;                      // same (legacy default) stream
    cudaLaunchAttribute attrs[1];
    attrs[0].id = cudaLaunchAttributeProgrammaticStreamSerialization;
    attrs[0].val.programmaticStreamSerializationAllowed = 1;
    cfg.attrs = attrs;
    cfg.numAttrs = 1;
    cudaLaunchKernelEx(&cfg, attn_divide_kernel, out);
}